// round 1
// baseline (speedup 1.0000x reference)
#include <cuda_runtime.h>
#include <cuda_bf16.h>
#include <cstdint>

// Problem constants
#define Bq   4
#define Nq   256
#define HIDq 256
#define Eq   64
#define Hq   4
#define Dq   32
#define OUTq 128      // HID/2
#define AGGq 260      // H*(2D+1)
#define ROWS (Bq*Nq)  // 1024

// Scratch (static device allocations are allowed)
__device__ float g_qk[ROWS * Hq * Eq];     // [row][h*64+e]
__device__ float g_multi[ROWS * AGGq];     // [row][h*65+k]

// ---------------- f32x2 helpers (Blackwell packed fp32) ----------------
__device__ __forceinline__ unsigned long long pack2(float a, float b) {
    unsigned long long r;
    asm("mov.b64 %0, {%1, %2};" : "=l"(r) : "f"(a), "f"(b));
    return r;
}
__device__ __forceinline__ void unpack2(unsigned long long v, float& a, float& b) {
    asm("mov.b64 {%0, %1}, %2;" : "=f"(a), "=f"(b) : "l"(v));
}
__device__ __forceinline__ unsigned long long fma2(unsigned long long a,
                                                   unsigned long long b,
                                                   unsigned long long c) {
    unsigned long long d;
    asm("fma.rn.f32x2 %0, %1, %2, %3;" : "=l"(d) : "l"(a), "l"(b), "l"(c));
    return d;
}
__device__ __forceinline__ unsigned long long add2(unsigned long long a,
                                                   unsigned long long b) {
    unsigned long long d;
    asm("add.rn.f32x2 %0, %1, %2;" : "=l"(d) : "l"(a), "l"(b));
    return d;
}
__device__ __forceinline__ unsigned long long mul2(unsigned long long a,
                                                   unsigned long long b) {
    unsigned long long d;
    asm("mul.rn.f32x2 %0, %1, %2;" : "=l"(d) : "l"(a), "l"(b));
    return d;
}

// =======================================================================
// Kernel 1: qk[row][h][e] = sum_d (h_x[row]·W_Q[h*32+d]) * W_K[h*32+d][e]
// grid 128 blocks x 256 threads; each block does 8 rows.
// =======================================================================
__global__ __launch_bounds__(256)
void qk_kernel(const float* __restrict__ hx,
               const float* __restrict__ WQ,
               const float* __restrict__ WK) {
    __shared__ float s_hx[8][256];
    __shared__ float s_w[128][65];
    __shared__ float s_q[8][128];

    const int tid  = threadIdx.x;
    const int row0 = blockIdx.x * 8;

    // load 8 h_x rows (coalesced)
    for (int i = tid; i < 8 * 256; i += 256)
        s_hx[i >> 8][i & 255] = hx[row0 * 256 + i];
    __syncthreads();

    // q = h_x @ W_Q^T  (chunked over x)
    const int c  = tid & 127;
    const int rh = tid >> 7;
    float acc[4] = {0.f, 0.f, 0.f, 0.f};
    for (int ch = 0; ch < 4; ch++) {
        for (int i = tid; i < 128 * 64; i += 256) {
            int cc = i >> 6, j = i & 63;
            s_w[cc][j] = WQ[cc * 256 + ch * 64 + j];
        }
        __syncthreads();
        #pragma unroll 8
        for (int j = 0; j < 64; j++) {
            float w = s_w[c][j];
            #pragma unroll
            for (int k = 0; k < 4; k++)
                acc[k] += s_hx[rh * 4 + k][ch * 64 + j] * w;
        }
        __syncthreads();
    }
    #pragma unroll
    for (int k = 0; k < 4; k++) s_q[rh * 4 + k][c] = acc[k];
    __syncthreads();

    // load W_K [128][64]
    for (int i = tid; i < 128 * 64; i += 256)
        s_w[i >> 6][i & 63] = WK[i];
    __syncthreads();

    // qk: thread (h = tid/64, e = tid%64), all 8 rows
    const int h = tid >> 6;
    const int e = tid & 63;
    #pragma unroll
    for (int r = 0; r < 8; r++) {
        float s = 0.f;
        #pragma unroll 8
        for (int d = 0; d < 32; d++)
            s += s_q[r][h * 32 + d] * s_w[h * 32 + d][e];
        g_qk[(row0 + r) * 256 + h * 64 + e] = s;
    }
}

// =======================================================================
// Kernel 2 (main): per (b,n) row
//   - scores over m + softmax over H  (streaming, no m-reduction needed)
//   - fused V projection + attn*v sum + attn*v max (f32x2 packed)
// grid 1024 x 256 threads, dynamic smem.
// SMEM layout (floats):
//   s_hep [128 m-pairs][132]  : hep[m2][2e+comp] = h_e[m][e], rows padded
//   s_qk  [256]
//   s_attn[4*256]             : attn[h*256 + m]  (pairs are ull-aligned)
//   s_asum[4]
// =======================================================================
#define HEPS 132
#define SMEM_MAIN ((128 * HEPS + 256 + 1024 + 4) * 4)

__global__ __launch_bounds__(256, 2)
void main_kernel(const float* __restrict__ h_e,
                 const float* __restrict__ h_m,
                 const float* __restrict__ W_V) {
    extern __shared__ float sm[];
    float* s_hep  = sm;
    float* s_qk   = sm + 128 * HEPS;
    float* s_attn = s_qk + 256;
    float* s_asum = s_attn + 1024;

    const int bn  = blockIdx.x;
    const int tid = threadIdx.x;

    // ---- load phase ----
    const float4* src4 = (const float4*)(h_e + (size_t)bn * (Nq * Eq));
    #pragma unroll
    for (int it = 0; it < 16; it++) {
        int flat = tid + it * 256;          // float4 index, 0..4095
        int m  = flat >> 4;
        int e4 = (flat & 15) << 2;
        float4 v = src4[flat];
        float* dst = s_hep + (m >> 1) * HEPS + (m & 1);
        dst[(e4 + 0) * 2] = v.x;
        dst[(e4 + 1) * 2] = v.y;
        dst[(e4 + 2) * 2] = v.z;
        dst[(e4 + 3) * 2] = v.w;
    }
    s_qk[tid] = g_qk[bn * 256 + tid];
    if (tid < 4) s_asum[tid] = 0.f;
    const float maskv = h_m[bn];
    __syncthreads();

    // ---- scores + softmax over heads (thread = m) ----
    {
        const int m = tid;
        const float* hb = s_hep + (m >> 1) * HEPS + (m & 1);
        float s0 = 0.f, s1 = 0.f, s2 = 0.f, s3 = 0.f;
        #pragma unroll 8
        for (int e = 0; e < 64; e++) {
            float he = hb[e * 2];
            s0 += he * s_qk[e];
            s1 += he * s_qk[64 + e];
            s2 += he * s_qk[128 + e];
            s3 += he * s_qk[192 + e];
        }
        const float scal = 0.1767766952966369f;  // 1/sqrt(32)
        s0 *= scal; s1 *= scal; s2 *= scal; s3 *= scal;
        if (maskv == 0.f) {
            const float ninf = __int_as_float(0xff800000);
            s0 = s1 = s2 = s3 = ninf;
        }
        float mx = fmaxf(fmaxf(s0, s1), fmaxf(s2, s3));
        float e0 = __expf(s0 - mx), e1 = __expf(s1 - mx);
        float e2 = __expf(s2 - mx), e3 = __expf(s3 - mx);
        float r  = 1.f / (e0 + e1 + e2 + e3);
        float a0 = e0 * r, a1 = e1 * r, a2 = e2 * r, a3 = e3 * r;
        s_attn[0 * 256 + m] = a0;
        s_attn[1 * 256 + m] = a1;
        s_attn[2 * 256 + m] = a2;
        s_attn[3 * 256 + m] = a3;
        // attn_sum warp-reduce + smem atomics
        float t0 = a0, t1 = a1, t2 = a2, t3 = a3;
        #pragma unroll
        for (int off = 16; off; off >>= 1) {
            t0 += __shfl_xor_sync(0xffffffffu, t0, off);
            t1 += __shfl_xor_sync(0xffffffffu, t1, off);
            t2 += __shfl_xor_sync(0xffffffffu, t2, off);
            t3 += __shfl_xor_sync(0xffffffffu, t3, off);
        }
        if ((tid & 31) == 0) {
            atomicAdd(&s_asum[0], t0);
            atomicAdd(&s_asum[1], t1);
            atomicAdd(&s_asum[2], t2);
            atomicAdd(&s_asum[3], t3);
        }
    }
    __syncthreads();

    // ---- V projection + attn*v sum/max (f32x2) ----
    const int c  = tid >> 1;     // output channel 0..127
    const int eh = tid & 1;      // e-half (lane pair)
    const int h  = c >> 5;

    // W_V half-row, duplicated into f32x2 regs (once)
    unsigned long long wv2[32];
    {
        const float4* wvp = (const float4*)(W_V + c * 64 + eh * 32);
        #pragma unroll
        for (int j = 0; j < 8; j++) {
            float4 w = wvp[j];
            wv2[4 * j + 0] = pack2(w.x, w.x);
            wv2[4 * j + 1] = pack2(w.y, w.y);
            wv2[4 * j + 2] = pack2(w.z, w.z);
            wv2[4 * j + 3] = pack2(w.w, w.w);
        }
    }

    unsigned long long accs = 0ull;  // (0.f, 0.f)
    const float ninf = __int_as_float(0xff800000);
    float amax0 = ninf, amax1 = ninf;
    const unsigned long long* attnp =
        (const unsigned long long*)(s_attn + h * 256);

    for (int m2 = 0; m2 < 128; m2++) {
        const ulonglong2* hp =
            (const ulonglong2*)(s_hep + m2 * HEPS + eh * 64);
        unsigned long long va = 0ull, vb = 0ull, vc = 0ull, vd = 0ull;
        #pragma unroll
        for (int j = 0; j < 16; j += 4) {
            ulonglong2 u0 = hp[j + 0];
            ulonglong2 u1 = hp[j + 1];
            ulonglong2 u2 = hp[j + 2];
            ulonglong2 u3 = hp[j + 3];
            va = fma2(u0.x, wv2[2 * j + 0], va);
            vb = fma2(u0.y, wv2[2 * j + 1], vb);
            vc = fma2(u1.x, wv2[2 * j + 2], vc);
            vd = fma2(u1.y, wv2[2 * j + 3], vd);
            va = fma2(u2.x, wv2[2 * j + 4], va);
            vb = fma2(u2.y, wv2[2 * j + 5], vb);
            vc = fma2(u3.x, wv2[2 * j + 6], vc);
            vd = fma2(u3.y, wv2[2 * j + 7], vd);
        }
        unsigned long long v = add2(add2(va, vb), add2(vc, vd));
        unsigned long long o = __shfl_xor_sync(0xffffffffu, v, 1);
        unsigned long long vf = add2(v, o);         // full 64-e dot, both m's
        unsigned long long at = attnp[m2];          // (attn[m0], attn[m1])
        unsigned long long aw = mul2(vf, at);
        accs = add2(accs, aw);
        float awlo, awhi;
        unpack2(aw, awlo, awhi);
        amax0 = fmaxf(amax0, awlo);
        amax1 = fmaxf(amax1, awhi);
    }

    if (eh == 0) {
        float slo, shi;
        unpack2(accs, slo, shi);
        float ssum = slo + shi;
        float smax = fmaxf(amax0, amax1);
        int   d    = c & 31;
        float asum = s_asum[h] + 1e-8f;
        float* mrow = g_multi + (size_t)bn * AGGq + h * 65;
        mrow[d]      = ssum / asum;   // aggr_mean
        if (d == 0) mrow[32] = asum;  // attn_sum (+1e-8, matching reference)
        mrow[33 + d] = smax;          // aggr_max
    }
}

// =======================================================================
// Kernel 3: out[row] = multi[row] @ W_R^T   ([1024,260] @ [260,128])
// grid 128 x 256 threads; 8 rows per block, W_R staged through smem.
// =======================================================================
__global__ __launch_bounds__(256)
void out_kernel(const float* __restrict__ W_R, float* __restrict__ out) {
    __shared__ float s_multi[8][260];
    __shared__ float s_wr[128][66];

    const int tid  = threadIdx.x;
    const int row0 = blockIdx.x * 8;

    for (int i = tid; i < 8 * 260; i += 256)
        s_multi[i / 260][i % 260] = g_multi[row0 * 260 + i];

    const int o  = tid & 127;
    const int rh = tid >> 7;
    float acc[4] = {0.f, 0.f, 0.f, 0.f};

    for (int ch = 0; ch < 4; ch++) {
        int a0 = ch * 65;
        __syncthreads();
        for (int i = tid; i < 128 * 65; i += 256) {
            int oo = i / 65, j = i % 65;
            s_wr[oo][j] = W_R[oo * 260 + a0 + j];
        }
        __syncthreads();
        #pragma unroll 5
        for (int j = 0; j < 65; j++) {
            float w = s_wr[o][j];
            #pragma unroll
            for (int k = 0; k < 4; k++)
                acc[k] += s_multi[rh * 4 + k][a0 + j] * w;
        }
    }
    #pragma unroll
    for (int k = 0; k < 4; k++)
        out[(size_t)(row0 + rh * 4 + k) * 128 + o] = acc[k];
}

// =======================================================================
extern "C" void kernel_launch(void* const* d_in, const int* in_sizes, int n_in,
                              void* d_out, int out_size) {
    (void)in_sizes; (void)n_in; (void)out_size;
    const float* h_x = (const float*)d_in[0];
    const float* h_e = (const float*)d_in[1];
    const float* h_m = (const float*)d_in[2];
    const float* W_Q = (const float*)d_in[3];
    const float* W_K = (const float*)d_in[4];
    const float* W_V = (const float*)d_in[5];
    const float* W_R = (const float*)d_in[6];
    float* out = (float*)d_out;

    cudaFuncSetAttribute(main_kernel,
                         cudaFuncAttributeMaxDynamicSharedMemorySize,
                         SMEM_MAIN);

    qk_kernel<<<128, 256>>>(h_x, W_Q, W_K);
    main_kernel<<<ROWS, 256, SMEM_MAIN>>>(h_e, h_m, W_V);
    out_kernel<<<128, 256>>>(W_R, out);
}